// round 6
// baseline (speedup 1.0000x reference)
#include <cuda_runtime.h>
#include <math.h>

// Problem constants
#define BB   64
#define NN   4096
#define IND  256
#define SS   8
#define DD   256
#define ROWS (BB*SS)        // 512
#define NCH  32             // attention chunks
#define NTT  128            // n's per chunk (tile fully smem-resident)

// -------- scratch (device globals; no allocation allowed) --------
__device__ float g_slots [ROWS*DD];
__device__ float g_qW    [ROWS*IND];
__device__ float g_upart [NCH*ROWS*IND];   // unnormalized U partials (16 MB)
__device__ float g_m     [NCH*ROWS];       // per-chunk max
__device__ float g_l     [NCH*ROWS];       // per-chunk exp-sum

// -------- reductions --------
__device__ __forceinline__ float warpSum(float v){
#pragma unroll
    for (int o = 16; o > 0; o >>= 1) v += __shfl_xor_sync(0xffffffffu, v, o);
    return v;
}
__device__ __forceinline__ float warpMax(float v){
#pragma unroll
    for (int o = 16; o > 0; o >>= 1) v = fmaxf(v, __shfl_xor_sync(0xffffffffu, v, o));
    return v;
}

// Block LayerNorm of 4 rows held column-wise: thread t holds v[r] = X[r][t].
__device__ __forceinline__ void block_ln4(const float v[4], float o[4],
                                          const float* __restrict__ g,
                                          const float* __restrict__ b, int t)
{
    __shared__ float part[8][4];
    __shared__ float stat[4];
    int w = t >> 5, l = t & 31;
#pragma unroll
    for (int r = 0; r < 4; ++r){
        float p = warpSum(v[r]);
        if (l == 0) part[w][r] = p;
    }
    __syncthreads();
    if (t < 32){
        int rr = l >> 3, ww = l & 7;
        float x = part[ww][rr];
        x += __shfl_xor_sync(0xffffffffu, x, 1);
        x += __shfl_xor_sync(0xffffffffu, x, 2);
        x += __shfl_xor_sync(0xffffffffu, x, 4);
        if (ww == 0) stat[rr] = x * (1.f/256.f);
    }
    __syncthreads();
    float d[4];
#pragma unroll
    for (int r = 0; r < 4; ++r) d[r] = v[r] - stat[r];
    __syncthreads();
#pragma unroll
    for (int r = 0; r < 4; ++r){
        float p = warpSum(d[r]*d[r]);
        if (l == 0) part[w][r] = p;
    }
    __syncthreads();
    if (t < 32){
        int rr = l >> 3, ww = l & 7;
        float x = part[ww][rr];
        x += __shfl_xor_sync(0xffffffffu, x, 1);
        x += __shfl_xor_sync(0xffffffffu, x, 2);
        x += __shfl_xor_sync(0xffffffffu, x, 4);
        if (ww == 0) stat[rr] = rsqrtf(x * (1.f/256.f) + 1e-5f);
    }
    __syncthreads();
    float gg = g[t], bb = b[t];
#pragma unroll
    for (int r = 0; r < 4; ++r) o[r] = d[r] * stat[r] * gg + bb;
}

// -------- slots = mu + sigma * noise --------
__global__ void init_slots_kernel(const float* __restrict__ noise,
                                  const float* __restrict__ mu,
                                  const float* __restrict__ sigma,
                                  float* __restrict__ slots){
    int i  = blockIdx.x * 256 + threadIdx.x;
    int sd = i & (SS*DD - 1);
    slots[i] = mu[sd] + sigma[sd] * noise[i];
}

// ============ PRE: LN(slots) -> q=ln@Wq^T+bq -> qW=(q@Wk)*inv_sqrt_d ============
__global__ __launch_bounds__(256) void pre_kernel(
        const float* __restrict__ slots,
        const float* __restrict__ lng, const float* __restrict__ lnb,
        const float* __restrict__ Wq,  const float* __restrict__ bq,
        const float* __restrict__ Wk,
        float* __restrict__ qW)
{
    int r0 = blockIdx.x * 4;
    int t  = threadIdx.x;
    __shared__ float s_ln[4][DD];
    __shared__ float s_q [4][DD];

    float v[4];
#pragma unroll
    for (int r = 0; r < 4; ++r) v[r] = slots[(size_t)(r0+r)*DD + t];
    float o[4];
    block_ln4(v, o, lng, lnb, t);
#pragma unroll
    for (int r = 0; r < 4; ++r) s_ln[r][t] = o[r];
    __syncthreads();

    {   // q[r, n=t] = s_ln[r] . Wq[t,:] + bq[t]
        const float4* wrow = reinterpret_cast<const float4*>(Wq + (size_t)t*DD);
        float a0=0.f, a1=0.f, a2=0.f, a3=0.f;
#pragma unroll 8
        for (int k4 = 0; k4 < 64; ++k4){
            float4 wv = __ldg(&wrow[k4]);
            int k = k4*4;
            a0 += s_ln[0][k]*wv.x + s_ln[0][k+1]*wv.y + s_ln[0][k+2]*wv.z + s_ln[0][k+3]*wv.w;
            a1 += s_ln[1][k]*wv.x + s_ln[1][k+1]*wv.y + s_ln[1][k+2]*wv.z + s_ln[1][k+3]*wv.w;
            a2 += s_ln[2][k]*wv.x + s_ln[2][k+1]*wv.y + s_ln[2][k+2]*wv.z + s_ln[2][k+3]*wv.w;
            a3 += s_ln[3][k]*wv.x + s_ln[3][k+1]*wv.y + s_ln[3][k+2]*wv.z + s_ln[3][k+3]*wv.w;
        }
        float bv = __ldg(&bq[t]);
        s_q[0][t] = a0 + bv; s_q[1][t] = a1 + bv;
        s_q[2][t] = a2 + bv; s_q[3][t] = a3 + bv;
    }
    __syncthreads();

    {   // qW[r, e=t] = (s_q[r] @ Wk[:,t]) / 16
        float c0=0.f, c1=0.f, c2=0.f, c3=0.f;
#pragma unroll 8
        for (int d = 0; d < DD; ++d){
            float wv = __ldg(&Wk[(size_t)d*IND + t]);
            c0 += s_q[0][d]*wv; c1 += s_q[1][d]*wv;
            c2 += s_q[2][d]*wv; c3 += s_q[3][d]*wv;
        }
        qW[(size_t)(r0+0)*IND + t] = c0 * 0.0625f;
        qW[(size_t)(r0+1)*IND + t] = c1 * 0.0625f;
        qW[(size_t)(r0+2)*IND + t] = c2 * 0.0625f;
        qW[(size_t)(r0+3)*IND + t] = c3 * 0.0625f;
    }
}

// ============ FUSED attention, smem-resident X tile (inputs read ONCE) ============
// grid (B=64, NCH=32), 256 threads, dynamic smem ~149.5 KB (1 block/SM).
// Xs holds X[128 n][256 k] XOR-swizzled: element (n,k) at Xs[k*128 + (n ^ (k&31))]
// -> conflict-free for both fixed-k (phase 1) and fixed-n... (phase 3) patterns.
__global__ __launch_bounds__(256) void attn_kernel(
        const float* __restrict__ qW,
        const float* __restrict__ inputs,
        float* __restrict__ upart,
        float* __restrict__ mbuf,
        float* __restrict__ lbuf)
{
    extern __shared__ float dsm[];
    float* Xs   = dsm;                 // 32768 floats (128 KB)
    float* qT   = dsm + 32768;         // [k][s] 256*8
    float* lg   = qT  + 2048;          // [s][n] 8*128
    float* at_T = lg  + 1024;          // [n][12] exp weights, float4-aligned rows

    int b = blockIdx.x, ch = blockIdx.y;
    int t = threadIdx.x;
    int w = t >> 5, l = t & 31;

    // ---- stage X tile [128 n x 256 k] and qT ----
    const size_t base = ((size_t)b*NN + (size_t)ch*NTT) * IND;
#pragma unroll
    for (int p = 0; p < 32; ++p){
        int idx = t + p*256;
        int n = idx >> 6, k4 = idx & 63;
        float4 xv = __ldg((const float4*)&inputs[base + (size_t)n*IND + k4*4]);
        int k = k4*4;
        Xs[(k+0)*NTT + (n ^ ((k+0)&31))] = xv.x;
        Xs[(k+1)*NTT + (n ^ ((k+1)&31))] = xv.y;
        Xs[(k+2)*NTT + (n ^ ((k+2)&31))] = xv.z;
        Xs[(k+3)*NTT + (n ^ ((k+3)&31))] = xv.w;
    }
#pragma unroll
    for (int p = 0; p < 8; ++p){
        int idx = t + p*256;
        int s = idx >> 8, k = idx & 255;
        qT[k*8 + s] = qW[(size_t)b*(SS*IND) + idx];
    }
    __syncthreads();

    // ---- phase 1: logits; thread = (n = t&127, k-half = t>>7), 8 s accumulators ----
    {
        int n  = t & 127;
        int kh = t >> 7;
        float acc[8] = {};
        int k0 = kh * 128;
#pragma unroll 4
        for (int k = k0; k < k0 + 128; ++k){
            float x = Xs[k*NTT + (n ^ (k & 31))];
            float4 qa = *(const float4*)&qT[k*8];
            float4 qb = *(const float4*)&qT[k*8 + 4];
            acc[0] += x*qa.x; acc[1] += x*qa.y; acc[2] += x*qa.z; acc[3] += x*qa.w;
            acc[4] += x*qb.x; acc[5] += x*qb.y; acc[6] += x*qb.z; acc[7] += x*qb.w;
        }
        if (kh == 0){
#pragma unroll
            for (int s = 0; s < 8; ++s) lg[s*NTT + n] = acc[s];
        }
        __syncthreads();
        if (kh == 1){
#pragma unroll
            for (int s = 0; s < 8; ++s) lg[s*NTT + n] += acc[s];
        }
        __syncthreads();
    }

    // ---- phase 2: per-chunk softmax; warp w owns slot s=w ----
    {
        float v0 = lg[w*NTT + l      ];
        float v1 = lg[w*NTT + l + 32 ];
        float v2 = lg[w*NTT + l + 64 ];
        float v3 = lg[w*NTT + l + 96 ];
        float mv = warpMax(fmaxf(fmaxf(v0, v1), fmaxf(v2, v3)));
        float e0 = __expf(v0 - mv), e1 = __expf(v1 - mv);
        float e2 = __expf(v2 - mv), e3 = __expf(v3 - mv);
        at_T[(l      )*12 + w] = e0;
        at_T[(l + 32 )*12 + w] = e1;
        at_T[(l + 64 )*12 + w] = e2;
        at_T[(l + 96 )*12 + w] = e3;
        float sum = warpSum(e0 + e1 + e2 + e3);
        if (l == 0){
            int row = b*SS + w;
            mbuf[(size_t)ch*ROWS + row] = mv;
            lbuf[(size_t)ch*ROWS + row] = sum;
        }
    }
    __syncthreads();

    // ---- phase 3: Ubar[s][e=t] = sum_n at[n][s] * X[n][e] (all smem) ----
    {
        float acc[8] = {};
        int eb = t * NTT;
        int em = t & 31;
#pragma unroll 4
        for (int n = 0; n < NTT; ++n){
            float x = Xs[eb + (n ^ em)];
            float4 a0 = *(const float4*)&at_T[n*12];
            float4 a1 = *(const float4*)&at_T[n*12 + 4];
            acc[0] += a0.x*x; acc[1] += a0.y*x; acc[2] += a0.z*x; acc[3] += a0.w*x;
            acc[4] += a1.x*x; acc[5] += a1.y*x; acc[6] += a1.z*x; acc[7] += a1.w*x;
        }
#pragma unroll
        for (int s = 0; s < 8; ++s)
            upart[((size_t)ch*ROWS + b*SS + s)*IND + t] = acc[s];
    }
}

// ============ tile_gemm256: acc[r] = sum_k sA[r][k] * W[t][k], W staged via smem ======
// W row-major [256 out][256 k]. 256 threads; thread t owns output column t.
__device__ __forceinline__ void tile_gemm256(
        const float (*sA)[DD],
        const float* __restrict__ W,
        float* __restrict__ sWt,     // staging [32][257]
        float acc[4], int t)
{
    acc[0] = acc[1] = acc[2] = acc[3] = 0.f;
    for (int kt = 0; kt < 256; kt += 32){
        __syncthreads();
#pragma unroll
        for (int p = 0; p < 8; ++p){
            int idx  = t + p*256;
            int orow = idx >> 3, k4 = idx & 7;
            float4 wv = __ldg((const float4*)&W[(size_t)orow*DD + kt + k4*4]);
            sWt[(k4*4+0)*257 + orow] = wv.x;
            sWt[(k4*4+1)*257 + orow] = wv.y;
            sWt[(k4*4+2)*257 + orow] = wv.z;
            sWt[(k4*4+3)*257 + orow] = wv.w;
        }
        __syncthreads();
#pragma unroll
        for (int kk4 = 0; kk4 < 8; ++kk4){
            float4 a0 = *(const float4*)&sA[0][kt + kk4*4];
            float4 a1 = *(const float4*)&sA[1][kt + kk4*4];
            float4 a2 = *(const float4*)&sA[2][kt + kk4*4];
            float4 a3 = *(const float4*)&sA[3][kt + kk4*4];
            float x0 = sWt[(kk4*4+0)*257 + t];
            float x1 = sWt[(kk4*4+1)*257 + t];
            float x2 = sWt[(kk4*4+2)*257 + t];
            float x3 = sWt[(kk4*4+3)*257 + t];
            acc[0] += a0.x*x0 + a0.y*x1 + a0.z*x2 + a0.w*x3;
            acc[1] += a1.x*x0 + a1.y*x1 + a1.z*x2 + a1.w*x3;
            acc[2] += a2.x*x0 + a2.y*x1 + a2.z*x2 + a2.w*x3;
            acc[3] += a3.x*x0 + a3.y*x1 + a3.z*x2 + a3.w*x3;
        }
    }
}

// ============ POST: flash-combine -> Wv -> GRU+resid -> LN -> MLP+resid ============
// 128 blocks x 256 threads, 4 rows. All GEMMs via smem-staged tile_gemm256.
__global__ __launch_bounds__(256) void post_kernel(
        const float* __restrict__ upart,
        const float* __restrict__ mbuf, const float* __restrict__ lbuf,
        const float* __restrict__ Wv,   const float* __restrict__ bv,
        const float* __restrict__ W_ih, const float* __restrict__ b_ih,
        const float* __restrict__ W_hh, const float* __restrict__ b_hh,
        const float* __restrict__ lng,  const float* __restrict__ lnb,
        const float* __restrict__ W1,   const float* __restrict__ b1,
        const float* __restrict__ W2,   const float* __restrict__ b2,
        const float* __restrict__ slots_in,
        float* __restrict__ dst)
{
    int r0 = blockIdx.x * 4;
    int t  = threadIdx.x;
    int w  = t >> 5, l = t & 31;

    __shared__ float sBufA[4][DD];     // sU, later sln
    __shared__ float sprev[4][DD];
    __shared__ float sBufB[4][DD];     // supd, later shid
    __shared__ float sWt[32*257];
    __shared__ float ssc[4][33];
    __shared__ float sinv[4];

    // 1. per-row combine scales (warps 0-3; lane = chunk)
    if (w < 4){
        int row = r0 + w;
        float mv = __ldg(&mbuf[(size_t)l*ROWS + row]);
        float mm = warpMax(mv);
        float e  = __expf(mv - mm);
        float ls = warpSum(__ldg(&lbuf[(size_t)l*ROWS + row]) * e);
        ssc[w][l] = e;
        if (l == 0) sinv[w] = 1.f / ls;
    }
    __syncthreads();

    // 2. U = (sum_ch Ubar_ch * sc_ch) * inv ; load slots_prev
#pragma unroll
    for (int r = 0; r < 4; ++r){
        int row = r0 + r;
        float a = 0.f;
#pragma unroll
        for (int ch = 0; ch < NCH; ++ch)
            a += __ldg(&upart[((size_t)ch*ROWS + row)*IND + t]) * ssc[r][ch];
        sBufA[r][t] = a * sinv[r];
        sprev[r][t] = slots_in[(size_t)row*DD + t];
    }
    // (leading sync inside tile_gemm256 orders these writes)

    // 3. upd = U @ Wv^T + bv
    float acc[4];
    tile_gemm256(sBufA, Wv, sWt, acc, t);
    {
        float bb = __ldg(&bv[t]);
#pragma unroll
        for (int r = 0; r < 4; ++r) sBufB[r][t] = acc[r] + bb;
    }

    // 4. GRU gates in registers: thread t owns cols t, t+256, t+512
    float gi[3][4], gh[3][4];
#pragma unroll
    for (int j = 0; j < 3; ++j){
        tile_gemm256(sBufB, W_ih + (size_t)j*DD*DD, sWt, acc, t);
        float bb = __ldg(&b_ih[t + j*256]);
#pragma unroll
        for (int r = 0; r < 4; ++r) gi[j][r] = acc[r] + bb;
    }
#pragma unroll
    for (int j = 0; j < 3; ++j){
        tile_gemm256(sprev, W_hh + (size_t)j*DD*DD, sWt, acc, t);
        float bb = __ldg(&b_hh[t + j*256]);
#pragma unroll
        for (int r = 0; r < 4; ++r) gh[j][r] = acc[r] + bb;
    }

    // 5. GRU cell + residual
    float vnew[4];
#pragma unroll
    for (int r = 0; r < 4; ++r){
        float rr = 1.f / (1.f + expf(-(gi[0][r] + gh[0][r])));
        float zz = 1.f / (1.f + expf(-(gi[1][r] + gh[1][r])));
        float nn = tanhf(gi[2][r] + rr*gh[2][r]);
        float h  = sprev[r][t];
        vnew[r]  = h + (1.f - zz)*nn + zz*h;
    }
    __syncthreads();   // everyone done with gemm reads before LN reuses barriers

    // 6. LN -> sBufA (sln)
    float lnv[4];
    block_ln4(vnew, lnv, lng, lnb, t);
#pragma unroll
    for (int r = 0; r < 4; ++r) sBufA[r][t] = lnv[r];

    // 7. hidden = relu(sln @ W1^T + b1) -> sBufB
    tile_gemm256(sBufA, W1, sWt, acc, t);
    {
        float bb = __ldg(&b1[t]);
#pragma unroll
        for (int r = 0; r < 4; ++r) sBufB[r][t] = fmaxf(acc[r] + bb, 0.f);
    }

    // 8. out = vnew + hidden @ W2^T + b2
    tile_gemm256(sBufB, W2, sWt, acc, t);
    {
        float bb = __ldg(&b2[t]);
#pragma unroll
        for (int r = 0; r < 4; ++r)
            dst[(size_t)(r0+r)*DD + t] = vnew[r] + acc[r] + bb;
    }
}

// ------------------------- host launcher -------------------------
extern "C" void kernel_launch(void* const* d_in, const int* in_sizes, int n_in,
                              void* d_out, int out_size)
{
    const float* inputs = (const float*)d_in[0];
    const float* noise  = (const float*)d_in[1];
    const float* s_mu   = (const float*)d_in[2];
    const float* s_sig  = (const float*)d_in[3];
    const float* Wq = (const float*)d_in[4];  const float* bq = (const float*)d_in[5];
    const float* Wk = (const float*)d_in[6];  /* bk = d_in[7] : dead (softmax shift-invariance) */
    const float* Wv = (const float*)d_in[8];  const float* bv = (const float*)d_in[9];
    const float* W_ih = (const float*)d_in[10]; const float* b_ih = (const float*)d_in[11];
    const float* W_hh = (const float*)d_in[12]; const float* b_hh = (const float*)d_in[13];
    const float* W1 = (const float*)d_in[14]; const float* b1 = (const float*)d_in[15];
    const float* W2 = (const float*)d_in[16]; const float* b2 = (const float*)d_in[17];
    const float* lnsg = (const float*)d_in[18]; const float* lnsb = (const float*)d_in[19];
    const float* lnmg = (const float*)d_in[20]; const float* lnmb = (const float*)d_in[21];
    float* out = (float*)d_out;
    (void)in_sizes; (void)n_in; (void)out_size;

    float *slots, *qW, *upart, *mbuf, *lbuf;
    cudaGetSymbolAddress((void**)&slots, g_slots);
    cudaGetSymbolAddress((void**)&qW,    g_qW);
    cudaGetSymbolAddress((void**)&upart, g_upart);
    cudaGetSymbolAddress((void**)&mbuf,  g_m);
    cudaGetSymbolAddress((void**)&lbuf,  g_l);

    const int ATTN_SMEM = (32768 + 2048 + 1024 + 128*12) * 4;  // 149,504 B
    cudaFuncSetAttribute(attn_kernel, cudaFuncAttributeMaxDynamicSharedMemorySize, ATTN_SMEM);

    dim3 gBN(BB, NCH);

    init_slots_kernel<<<ROWS, 256>>>(noise, s_mu, s_sig, slots);

    for (int it = 0; it < 3; ++it){
        pre_kernel<<<ROWS/4, 256>>>(slots, lnsg, lnsb, Wq, bq, Wk, qW);
        attn_kernel<<<gBN, 256, ATTN_SMEM>>>(qW, inputs, upart, mbuf, lbuf);
        float* dst = (it == 2) ? out : slots;
        post_kernel<<<ROWS/4, 256>>>(upart, mbuf, lbuf, Wv, bv, W_ih, b_ih, W_hh, b_hh,
                                     lnmg, lnmb, W1, b1, W2, b2, slots, dst);
    }
}

// round 7
// speedup vs baseline: 1.4551x; 1.4551x over previous
#include <cuda_runtime.h>
#include <math.h>
#include <stdint.h>

// Problem constants
#define BB   64
#define NN   4096
#define IND  256
#define SS   8
#define DD   256
#define ROWS (BB*SS)        // 512
#define NG   8              // attention groups (blocks.y)
#define TN   64             // n's per tile
#define NTILE 8             // tiles per block (NG*NTILE*TN = 4096)

// -------- scratch (device globals; no allocation allowed) --------
__device__ float g_slots [ROWS*DD];
__device__ float g_qW    [ROWS*IND];
__device__ float g_upart [NG*ROWS*IND];   // unnormalized U partials (4 MB)
__device__ float g_m     [NG*ROWS];
__device__ float g_l     [NG*ROWS];

// -------- reductions --------
__device__ __forceinline__ float warpSum(float v){
#pragma unroll
    for (int o = 16; o > 0; o >>= 1) v += __shfl_xor_sync(0xffffffffu, v, o);
    return v;
}
__device__ __forceinline__ float warpMax(float v){
#pragma unroll
    for (int o = 16; o > 0; o >>= 1) v = fmaxf(v, __shfl_xor_sync(0xffffffffu, v, o));
    return v;
}

// Block LayerNorm of 4 rows held column-wise: thread t holds v[r] = X[r][t].
__device__ __forceinline__ void block_ln4(const float v[4], float o[4],
                                          const float* __restrict__ g,
                                          const float* __restrict__ b, int t)
{
    __shared__ float part[8][4];
    __shared__ float stat[4];
    int w = t >> 5, l = t & 31;
#pragma unroll
    for (int r = 0; r < 4; ++r){
        float p = warpSum(v[r]);
        if (l == 0) part[w][r] = p;
    }
    __syncthreads();
    if (t < 32){
        int rr = l >> 3, ww = l & 7;
        float x = part[ww][rr];
        x += __shfl_xor_sync(0xffffffffu, x, 1);
        x += __shfl_xor_sync(0xffffffffu, x, 2);
        x += __shfl_xor_sync(0xffffffffu, x, 4);
        if (ww == 0) stat[rr] = x * (1.f/256.f);
    }
    __syncthreads();
    float d[4];
#pragma unroll
    for (int r = 0; r < 4; ++r) d[r] = v[r] - stat[r];
    __syncthreads();
#pragma unroll
    for (int r = 0; r < 4; ++r){
        float p = warpSum(d[r]*d[r]);
        if (l == 0) part[w][r] = p;
    }
    __syncthreads();
    if (t < 32){
        int rr = l >> 3, ww = l & 7;
        float x = part[ww][rr];
        x += __shfl_xor_sync(0xffffffffu, x, 1);
        x += __shfl_xor_sync(0xffffffffu, x, 2);
        x += __shfl_xor_sync(0xffffffffu, x, 4);
        if (ww == 0) stat[rr] = rsqrtf(x * (1.f/256.f) + 1e-5f);
    }
    __syncthreads();
    float gg = g[t], bb = b[t];
#pragma unroll
    for (int r = 0; r < 4; ++r) o[r] = d[r] * stat[r] * gg + bb;
}

// -------- slots = mu + sigma * noise --------
__global__ void init_slots_kernel(const float* __restrict__ noise,
                                  const float* __restrict__ mu,
                                  const float* __restrict__ sigma,
                                  float* __restrict__ slots){
    int i  = blockIdx.x * 256 + threadIdx.x;
    int sd = i & (SS*DD - 1);
    slots[i] = mu[sd] + sigma[sd] * noise[i];
}

// ============ PRE: LN(slots) -> q=ln@Wq^T+bq -> qW=(q@Wk)*inv_sqrt_d ============
__global__ __launch_bounds__(256) void pre_kernel(
        const float* __restrict__ slots,
        const float* __restrict__ lng, const float* __restrict__ lnb,
        const float* __restrict__ Wq,  const float* __restrict__ bq,
        const float* __restrict__ Wk,
        float* __restrict__ qW)
{
    int r0 = blockIdx.x * 4;
    int t  = threadIdx.x;
    __shared__ float s_ln[4][DD];
    __shared__ float s_q [4][DD];

    float v[4];
#pragma unroll
    for (int r = 0; r < 4; ++r) v[r] = slots[(size_t)(r0+r)*DD + t];
    float o[4];
    block_ln4(v, o, lng, lnb, t);
#pragma unroll
    for (int r = 0; r < 4; ++r) s_ln[r][t] = o[r];
    __syncthreads();

    {   // q[r, n=t] = s_ln[r] . Wq[t,:] + bq[t]
        const float4* wrow = reinterpret_cast<const float4*>(Wq + (size_t)t*DD);
        float a0=0.f, a1=0.f, a2=0.f, a3=0.f;
#pragma unroll 8
        for (int k4 = 0; k4 < 64; ++k4){
            float4 wv = __ldg(&wrow[k4]);
            int k = k4*4;
            a0 += s_ln[0][k]*wv.x + s_ln[0][k+1]*wv.y + s_ln[0][k+2]*wv.z + s_ln[0][k+3]*wv.w;
            a1 += s_ln[1][k]*wv.x + s_ln[1][k+1]*wv.y + s_ln[1][k+2]*wv.z + s_ln[1][k+3]*wv.w;
            a2 += s_ln[2][k]*wv.x + s_ln[2][k+1]*wv.y + s_ln[2][k+2]*wv.z + s_ln[2][k+3]*wv.w;
            a3 += s_ln[3][k]*wv.x + s_ln[3][k+1]*wv.y + s_ln[3][k+2]*wv.z + s_ln[3][k+3]*wv.w;
        }
        float bv = __ldg(&bq[t]);
        s_q[0][t] = a0 + bv; s_q[1][t] = a1 + bv;
        s_q[2][t] = a2 + bv; s_q[3][t] = a3 + bv;
    }
    __syncthreads();

    {   // qW[r, e=t] = (s_q[r] @ Wk[:,t]) / 16
        float c0=0.f, c1=0.f, c2=0.f, c3=0.f;
#pragma unroll 8
        for (int d = 0; d < DD; ++d){
            float wv = __ldg(&Wk[(size_t)d*IND + t]);
            c0 += s_q[0][d]*wv; c1 += s_q[1][d]*wv;
            c2 += s_q[2][d]*wv; c3 += s_q[3][d]*wv;
        }
        qW[(size_t)(r0+0)*IND + t] = c0 * 0.0625f;
        qW[(size_t)(r0+1)*IND + t] = c1 * 0.0625f;
        qW[(size_t)(r0+2)*IND + t] = c2 * 0.0625f;
        qW[(size_t)(r0+3)*IND + t] = c3 * 0.0625f;
    }
}

// ============ FLASH attention: cp.async double-buffered 64-n tiles ============
// grid (B=64, NG=8), 256 threads. Online softmax, register U accumulators.
// X tile stored as float4: slot(n, k4) at [n*64 + (k4 ^ n)] (XOR swizzle).
__global__ __launch_bounds__(256) void attn_kernel(
        const float* __restrict__ qW,
        const float* __restrict__ inputs,
        float* __restrict__ upart,
        float* __restrict__ mbuf,
        float* __restrict__ lbuf)
{
    extern __shared__ float dsm[];
    float* Xs  = dsm;                  // 2 * 16384 floats (128 KB)
    float* qT  = dsm + 32768;          // [k][s] 256*8
    float* lg4 = qT + 2048;            // [kq][s][n] 4*8*64
    float* atT = lg4 + 2048;           // [n][12] exp weights
    float* scs = atT + 768;            // [8] per-tile rescale

    int b = blockIdx.x, g = blockIdx.y;
    int t = threadIdx.x, w = t >> 5, l = t & 31;
    const int n_base = g * (NTILE*TN);

    // stage qT
#pragma unroll
    for (int p = 0; p < 8; ++p){
        int idx = t + p*256;
        qT[(idx & 255)*8 + (idx >> 8)] = qW[(size_t)b*2048 + idx];
    }

    // prefetch tile j into buffer buf (16 x cp.async 16B per thread)
    const float* src0 = inputs + ((size_t)b*NN + n_base)*IND;
#define PREFETCH(j, buf) do {                                                   \
        const float* _s = src0 + (size_t)(j)*TN*IND;                            \
        float* _d = Xs + (buf)*16384;                                           \
        _Pragma("unroll")                                                       \
        for (int p = 0; p < 16; ++p){                                           \
            int idx = t + p*256;                                                \
            int n = idx >> 6, k4 = idx & 63;                                    \
            uint32_t sa = (uint32_t)__cvta_generic_to_shared(                   \
                              &_d[(n*64 + (k4 ^ n))*4]);                        \
            asm volatile("cp.async.cg.shared.global [%0], [%1], 16;"            \
                         :: "r"(sa), "l"(_s + (size_t)n*IND + k4*4) : "memory");\
        }                                                                       \
        asm volatile("cp.async.commit_group;" ::: "memory");                    \
    } while(0)

    PREFETCH(0, 0);

    float m_run = -3.4e38f, l_run = 0.f;
    float uacc[8] = {};
    const int e4 = t >> 2, eo = t & 3;
    const int pn = t & 63, kq = t >> 6;

    for (int j = 0; j < NTILE; ++j){
        int buf = j & 1;
        if (j + 1 < NTILE){
            PREFETCH(j + 1, buf ^ 1);
            asm volatile("cp.async.wait_group 1;" ::: "memory");
        } else {
            asm volatile("cp.async.wait_group 0;" ::: "memory");
        }
        __syncthreads();
        const float* Xb = Xs + buf*16384;

        // ---- phase 1: logits; thread = (n = t&63, kq = t>>6) ----
        {
            float acc[8] = {};
#pragma unroll
            for (int i = 0; i < 16; ++i){
                int k4 = kq*16 + i;
                float4 x4 = *(const float4*)&Xb[(pn*64 + (k4 ^ pn))*4];
                int k = k4*4;
                float xv[4] = {x4.x, x4.y, x4.z, x4.w};
#pragma unroll
                for (int d = 0; d < 4; ++d){
                    float4 qa = *(const float4*)&qT[(k+d)*8];
                    float4 qb = *(const float4*)&qT[(k+d)*8 + 4];
                    acc[0] += xv[d]*qa.x; acc[1] += xv[d]*qa.y;
                    acc[2] += xv[d]*qa.z; acc[3] += xv[d]*qa.w;
                    acc[4] += xv[d]*qb.x; acc[5] += xv[d]*qb.y;
                    acc[6] += xv[d]*qb.z; acc[7] += xv[d]*qb.w;
                }
            }
#pragma unroll
            for (int s = 0; s < 8; ++s) lg4[(kq*8 + s)*64 + pn] = acc[s];
        }
        __syncthreads();

        // ---- phase 2: online softmax; warp w owns slot s=w ----
        {
            float t0 = 0.f, t1 = 0.f;
#pragma unroll
            for (int q = 0; q < 4; ++q){
                t0 += lg4[(q*8 + w)*64 + l];
                t1 += lg4[(q*8 + w)*64 + l + 32];
            }
            float mv = warpMax(fmaxf(t0, t1));
            float m_new = fmaxf(m_run, mv);
            float e0 = __expf(t0 - m_new), e1 = __expf(t1 - m_new);
            atT[l*12 + w]        = e0;
            atT[(l + 32)*12 + w] = e1;
            float sum = warpSum(e0 + e1);
            float sc  = __expf(m_run - m_new);
            l_run = l_run*sc + sum;
            m_run = m_new;
            if (l == 0) scs[w] = sc;
        }
        __syncthreads();

        // ---- phase 3: U accumulation with flash rescale ----
        {
            float4 s0 = *(const float4*)&scs[0];
            float4 s1 = *(const float4*)&scs[4];
            uacc[0] *= s0.x; uacc[1] *= s0.y; uacc[2] *= s0.z; uacc[3] *= s0.w;
            uacc[4] *= s1.x; uacc[5] *= s1.y; uacc[6] *= s1.z; uacc[7] *= s1.w;
#pragma unroll 2
            for (int n = 0; n < TN; ++n){
                float x = Xb[(n*64 + (e4 ^ n))*4 + eo];
                float4 a0 = *(const float4*)&atT[n*12];
                float4 a1 = *(const float4*)&atT[n*12 + 4];
                uacc[0] += a0.x*x; uacc[1] += a0.y*x; uacc[2] += a0.z*x; uacc[3] += a0.w*x;
                uacc[4] += a1.x*x; uacc[5] += a1.y*x; uacc[6] += a1.z*x; uacc[7] += a1.w*x;
            }
        }
        __syncthreads();
    }
#undef PREFETCH

#pragma unroll
    for (int s = 0; s < 8; ++s)
        upart[((size_t)g*ROWS + b*SS + s)*IND + t] = uacc[s];
    if (l == 0){
        int row = b*SS + w;
        mbuf[(size_t)g*ROWS + row] = m_run;
        lbuf[(size_t)g*ROWS + row] = l_run;
    }
}

// ============ tile_gemm256_db: register-double-buffered weight staging ============
// acc[r] = sum_k sA[r][k] * W[t][k].  W row-major [256][256].
__device__ __forceinline__ void tile_gemm256_db(
        const float (*sA)[DD],
        const float* __restrict__ W,
        float* __restrict__ sWt,     // staging [32][257]
        float acc[4], int t)
{
    const float4* Wp = reinterpret_cast<const float4*>(W);
    float4 r[8];
#pragma unroll
    for (int p = 0; p < 8; ++p){
        int idx = t + p*256;
        r[p] = __ldg(&Wp[(size_t)(idx >> 3)*64 + (idx & 7)]);
    }
    acc[0] = acc[1] = acc[2] = acc[3] = 0.f;

    for (int kt = 0; kt < 8; ++kt){
        __syncthreads();
#pragma unroll
        for (int p = 0; p < 8; ++p){
            int idx  = t + p*256;
            int orow = idx >> 3, k4 = idx & 7;
            sWt[(k4*4+0)*257 + orow] = r[p].x;
            sWt[(k4*4+1)*257 + orow] = r[p].y;
            sWt[(k4*4+2)*257 + orow] = r[p].z;
            sWt[(k4*4+3)*257 + orow] = r[p].w;
        }
        __syncthreads();
        if (kt < 7){
#pragma unroll
            for (int p = 0; p < 8; ++p){
                int idx = t + p*256;
                r[p] = __ldg(&Wp[(size_t)(idx >> 3)*64 + (kt+1)*8 + (idx & 7)]);
            }
        }
        int kb = kt*32;
#pragma unroll
        for (int kk = 0; kk < 8; ++kk){
            float4 a0 = *(const float4*)&sA[0][kb + kk*4];
            float4 a1 = *(const float4*)&sA[1][kb + kk*4];
            float4 a2 = *(const float4*)&sA[2][kb + kk*4];
            float4 a3 = *(const float4*)&sA[3][kb + kk*4];
            float x0 = sWt[(kk*4+0)*257 + t];
            float x1 = sWt[(kk*4+1)*257 + t];
            float x2 = sWt[(kk*4+2)*257 + t];
            float x3 = sWt[(kk*4+3)*257 + t];
            acc[0] += a0.x*x0 + a0.y*x1 + a0.z*x2 + a0.w*x3;
            acc[1] += a1.x*x0 + a1.y*x1 + a1.z*x2 + a1.w*x3;
            acc[2] += a2.x*x0 + a2.y*x1 + a2.z*x2 + a2.w*x3;
            acc[3] += a3.x*x0 + a3.y*x1 + a3.z*x2 + a3.w*x3;
        }
    }
}

// ============ POST: flash-combine -> Wv -> GRU+resid -> LN -> MLP+resid ============
__global__ __launch_bounds__(256) void post_kernel(
        const float* __restrict__ upart,
        const float* __restrict__ mbuf, const float* __restrict__ lbuf,
        const float* __restrict__ Wv,   const float* __restrict__ bv,
        const float* __restrict__ W_ih, const float* __restrict__ b_ih,
        const float* __restrict__ W_hh, const float* __restrict__ b_hh,
        const float* __restrict__ lng,  const float* __restrict__ lnb,
        const float* __restrict__ W1,   const float* __restrict__ b1,
        const float* __restrict__ W2,   const float* __restrict__ b2,
        const float* __restrict__ slots_in,
        float* __restrict__ dst)
{
    int r0 = blockIdx.x * 4;
    int t  = threadIdx.x;
    int w  = t >> 5, l = t & 31;

    __shared__ float sBufA[4][DD];     // sU, later sln
    __shared__ float sprev[4][DD];
    __shared__ float sBufB[4][DD];     // supd, later shid
    __shared__ float sWt[32*257];
    __shared__ float ssc[4][9];
    __shared__ float sinv[4];

    // 1. per-row combine scales over NG=8 groups (warps 0-3, lanes 0-7)
    if (w < 4){
        int row = r0 + w;
        float mv = (l < 8) ? __ldg(&mbuf[(size_t)l*ROWS + row]) : -3.4e38f;
        float mm = mv;
        mm = fmaxf(mm, __shfl_xor_sync(0xffffffffu, mm, 1));
        mm = fmaxf(mm, __shfl_xor_sync(0xffffffffu, mm, 2));
        mm = fmaxf(mm, __shfl_xor_sync(0xffffffffu, mm, 4));
        float e  = (l < 8) ? __expf(mv - mm) : 0.f;
        float lv = (l < 8) ? __ldg(&lbuf[(size_t)l*ROWS + row]) * e : 0.f;
        lv += __shfl_xor_sync(0xffffffffu, lv, 1);
        lv += __shfl_xor_sync(0xffffffffu, lv, 2);
        lv += __shfl_xor_sync(0xffffffffu, lv, 4);
        if (l < 8) ssc[w][l] = e;
        if (l == 0) sinv[w] = 1.f / lv;
    }
    __syncthreads();

    // 2. U = (sum_g Ubar_g * sc_g) * inv ; load slots_prev
#pragma unroll
    for (int r = 0; r < 4; ++r){
        int row = r0 + r;
        float a = 0.f;
#pragma unroll
        for (int ch = 0; ch < NG; ++ch)
            a += __ldg(&upart[((size_t)ch*ROWS + row)*IND + t]) * ssc[r][ch];
        sBufA[r][t] = a * sinv[r];
        sprev[r][t] = slots_in[(size_t)row*DD + t];
    }
    // (leading sync inside tile_gemm256_db orders these writes)

    // 3. upd = U @ Wv^T + bv
    float acc[4];
    tile_gemm256_db(sBufA, Wv, sWt, acc, t);
    {
        float bb = __ldg(&bv[t]);
#pragma unroll
        for (int r = 0; r < 4; ++r) sBufB[r][t] = acc[r] + bb;
    }

    // 4. GRU gates in registers: thread t owns cols t, t+256, t+512
    float gi[3][4], gh[3][4];
#pragma unroll
    for (int j = 0; j < 3; ++j){
        tile_gemm256_db(sBufB, W_ih + (size_t)j*DD*DD, sWt, acc, t);
        float bb = __ldg(&b_ih[t + j*256]);
#pragma unroll
        for (int r = 0; r < 4; ++r) gi[j][r] = acc[r] + bb;
    }
#pragma unroll
    for (int j = 0; j < 3; ++j){
        tile_gemm256_db(sprev, W_hh + (size_t)j*DD*DD, sWt, acc, t);
        float bb = __ldg(&b_hh[t + j*256]);
#pragma unroll
        for (int r = 0; r < 4; ++r) gh[j][r] = acc[r] + bb;
    }

    // 5. GRU cell + residual
    float vnew[4];
#pragma unroll
    for (int r = 0; r < 4; ++r){
        float rr = 1.f / (1.f + expf(-(gi[0][r] + gh[0][r])));
        float zz = 1.f / (1.f + expf(-(gi[1][r] + gh[1][r])));
        float nn = tanhf(gi[2][r] + rr*gh[2][r]);
        float h  = sprev[r][t];
        vnew[r]  = h + (1.f - zz)*nn + zz*h;
    }
    __syncthreads();

    // 6. LN -> sBufA (sln)
    float lnv[4];
    block_ln4(vnew, lnv, lng, lnb, t);
#pragma unroll
    for (int r = 0; r < 4; ++r) sBufA[r][t] = lnv[r];

    // 7. hidden = relu(sln @ W1^T + b1) -> sBufB
    tile_gemm256_db(sBufA, W1, sWt, acc, t);
    {
        float bb = __ldg(&b1[t]);
#pragma unroll
        for (int r = 0; r < 4; ++r) sBufB[r][t] = fmaxf(acc[r] + bb, 0.f);
    }

    // 8. out = vnew + hidden @ W2^T + b2
    tile_gemm256_db(sBufB, W2, sWt, acc, t);
    {
        float bb = __ldg(&b2[t]);
#pragma unroll
        for (int r = 0; r < 4; ++r)
            dst[(size_t)(r0+r)*DD + t] = vnew[r] + acc[r] + bb;
    }
}

// ------------------------- host launcher -------------------------
extern "C" void kernel_launch(void* const* d_in, const int* in_sizes, int n_in,
                              void* d_out, int out_size)
{
    const float* inputs = (const float*)d_in[0];
    const float* noise  = (const float*)d_in[1];
    const float* s_mu   = (const float*)d_in[2];
    const float* s_sig  = (const float*)d_in[3];
    const float* Wq = (const float*)d_in[4];  const float* bq = (const float*)d_in[5];
    const float* Wk = (const float*)d_in[6];  /* bk = d_in[7] : dead (softmax shift-invariance) */
    const float* Wv = (const float*)d_in[8];  const float* bv = (const float*)d_in[9];
    const float* W_ih = (const float*)d_in[10]; const float* b_ih = (const float*)d_in[11];
    const float* W_hh = (const float*)d_in[12]; const float* b_hh = (const float*)d_in[13];
    const float* W1 = (const float*)d_in[14]; const float* b1 = (const float*)d_in[15];
    const float* W2 = (const float*)d_in[16]; const float* b2 = (const float*)d_in[17];
    const float* lnsg = (const float*)d_in[18]; const float* lnsb = (const float*)d_in[19];
    const float* lnmg = (const float*)d_in[20]; const float* lnmb = (const float*)d_in[21];
    float* out = (float*)d_out;
    (void)in_sizes; (void)n_in; (void)out_size;

    float *slots, *qW, *upart, *mbuf, *lbuf;
    cudaGetSymbolAddress((void**)&slots, g_slots);
    cudaGetSymbolAddress((void**)&qW,    g_qW);
    cudaGetSymbolAddress((void**)&upart, g_upart);
    cudaGetSymbolAddress((void**)&mbuf,  g_m);
    cudaGetSymbolAddress((void**)&lbuf,  g_l);

    const int ATTN_SMEM = (32768 + 2048 + 2048 + 768 + 8) * 4;  // 150,568 B
    cudaFuncSetAttribute(attn_kernel, cudaFuncAttributeMaxDynamicSharedMemorySize, ATTN_SMEM);

    dim3 gBN(BB, NG);

    init_slots_kernel<<<ROWS, 256>>>(noise, s_mu, s_sig, slots);

    for (int it = 0; it < 3; ++it){
        pre_kernel<<<ROWS/4, 256>>>(slots, lnsg, lnsb, Wq, bq, Wk, qW);
        attn_kernel<<<gBN, 256, ATTN_SMEM>>>(qW, inputs, upart, mbuf, lbuf);
        float* dst = (it == 2) ? out : slots;
        post_kernel<<<ROWS/4, 256>>>(upart, mbuf, lbuf, Wv, bv, W_ih, b_ih, W_hh, b_hh,
                                     lnmg, lnmb, W1, b1, W2, b2, slots, dst);
    }
}

// round 8
// speedup vs baseline: 1.5137x; 1.0403x over previous
#include <cuda_runtime.h>
#include <math.h>
#include <stdint.h>

// Problem constants
#define BB   64
#define NN   4096
#define IND  256
#define SS   8
#define DD   256
#define ROWS (BB*SS)        // 512
#define NG   8              // attention groups (blocks.y)
#define TN   64             // n's per tile
#define NTILE 8             // tiles per block

// -------- scratch (device globals; no allocation allowed) --------
__device__ float g_slots [ROWS*DD];
__device__ float g_qW    [ROWS*IND];
__device__ float g_upart [NG*ROWS*IND];   // unnormalized U partials (4 MB)
__device__ float g_m     [NG*ROWS];
__device__ float g_l     [NG*ROWS];

// -------- reductions --------
__device__ __forceinline__ float warpSum(float v){
#pragma unroll
    for (int o = 16; o > 0; o >>= 1) v += __shfl_xor_sync(0xffffffffu, v, o);
    return v;
}
__device__ __forceinline__ float warpMax(float v){
#pragma unroll
    for (int o = 16; o > 0; o >>= 1) v = fmaxf(v, __shfl_xor_sync(0xffffffffu, v, o));
    return v;
}

// -------- slots = mu + sigma * noise --------
__global__ void init_slots_kernel(const float* __restrict__ noise,
                                  const float* __restrict__ mu,
                                  const float* __restrict__ sigma,
                                  float* __restrict__ slots){
    int i  = blockIdx.x * 256 + threadIdx.x;
    int sd = i & (SS*DD - 1);
    slots[i] = mu[sd] + sigma[sd] * noise[i];
}

// Block LayerNorm (256-thread data path; callable from 256 OR 512 threads —
// warps >= 8 just pass through the barriers).
__device__ __forceinline__ void block_ln4(const float v[4], float o[4],
                                          const float* __restrict__ g,
                                          const float* __restrict__ b, int t)
{
    __shared__ float part[8][4];
    __shared__ float stat[4];
    int w = t >> 5, l = t & 31;
#pragma unroll
    for (int r = 0; r < 4; ++r){
        float p = warpSum(v[r]);
        if (l == 0 && w < 8) part[w][r] = p;
    }
    __syncthreads();
    if (t < 32){
        int rr = l >> 3, ww = l & 7;
        float x = part[ww][rr];
        x += __shfl_xor_sync(0xffffffffu, x, 1);
        x += __shfl_xor_sync(0xffffffffu, x, 2);
        x += __shfl_xor_sync(0xffffffffu, x, 4);
        if (ww == 0) stat[rr] = x * (1.f/256.f);
    }
    __syncthreads();
    float d[4];
#pragma unroll
    for (int r = 0; r < 4; ++r) d[r] = v[r] - stat[r];
    __syncthreads();
#pragma unroll
    for (int r = 0; r < 4; ++r){
        float p = warpSum(d[r]*d[r]);
        if (l == 0 && w < 8) part[w][r] = p;
    }
    __syncthreads();
    if (t < 32){
        int rr = l >> 3, ww = l & 7;
        float x = part[ww][rr];
        x += __shfl_xor_sync(0xffffffffu, x, 1);
        x += __shfl_xor_sync(0xffffffffu, x, 2);
        x += __shfl_xor_sync(0xffffffffu, x, 4);
        if (ww == 0) stat[rr] = rsqrtf(x * (1.f/256.f) + 1e-5f);
    }
    __syncthreads();
    int tc = t & 255;
    float gg = g[tc], bb = b[tc];
#pragma unroll
    for (int r = 0; r < 4; ++r) o[r] = d[r] * stat[r] * gg + bb;
}

// ============ PRE: LN(slots) -> q=ln@Wq^T+bq -> qW=(q@Wk)*inv_sqrt_d ============
__global__ __launch_bounds__(256) void pre_kernel(
        const float* __restrict__ slots,
        const float* __restrict__ lng, const float* __restrict__ lnb,
        const float* __restrict__ Wq,  const float* __restrict__ bq,
        const float* __restrict__ Wk,
        float* __restrict__ qW)
{
    int r0 = blockIdx.x * 4;
    int t  = threadIdx.x;
    __shared__ float s_ln[4][DD];
    __shared__ float s_q [4][DD];

    float v[4];
#pragma unroll
    for (int r = 0; r < 4; ++r) v[r] = slots[(size_t)(r0+r)*DD + t];
    float o[4];
    block_ln4(v, o, lng, lnb, t);
#pragma unroll
    for (int r = 0; r < 4; ++r) s_ln[r][t] = o[r];
    __syncthreads();

    {   // q[r, n=t] = s_ln[r] . Wq[t,:] + bq[t]
        const float4* wrow = reinterpret_cast<const float4*>(Wq + (size_t)t*DD);
        float a0=0.f, a1=0.f, a2=0.f, a3=0.f;
#pragma unroll 8
        for (int k4 = 0; k4 < 64; ++k4){
            float4 wv = __ldg(&wrow[k4]);
            int k = k4*4;
            a0 += s_ln[0][k]*wv.x + s_ln[0][k+1]*wv.y + s_ln[0][k+2]*wv.z + s_ln[0][k+3]*wv.w;
            a1 += s_ln[1][k]*wv.x + s_ln[1][k+1]*wv.y + s_ln[1][k+2]*wv.z + s_ln[1][k+3]*wv.w;
            a2 += s_ln[2][k]*wv.x + s_ln[2][k+1]*wv.y + s_ln[2][k+2]*wv.z + s_ln[2][k+3]*wv.w;
            a3 += s_ln[3][k]*wv.x + s_ln[3][k+1]*wv.y + s_ln[3][k+2]*wv.z + s_ln[3][k+3]*wv.w;
        }
        float bv = __ldg(&bq[t]);
        s_q[0][t] = a0 + bv; s_q[1][t] = a1 + bv;
        s_q[2][t] = a2 + bv; s_q[3][t] = a3 + bv;
    }
    __syncthreads();

    {   // qW[r, e=t] = (s_q[r] @ Wk[:,t]) / 16
        float c0=0.f, c1=0.f, c2=0.f, c3=0.f;
#pragma unroll 8
        for (int d = 0; d < DD; ++d){
            float wv = __ldg(&Wk[(size_t)d*IND + t]);
            c0 += s_q[0][d]*wv; c1 += s_q[1][d]*wv;
            c2 += s_q[2][d]*wv; c3 += s_q[3][d]*wv;
        }
        qW[(size_t)(r0+0)*IND + t] = c0 * 0.0625f;
        qW[(size_t)(r0+1)*IND + t] = c1 * 0.0625f;
        qW[(size_t)(r0+2)*IND + t] = c2 * 0.0625f;
        qW[(size_t)(r0+3)*IND + t] = c3 * 0.0625f;
    }
}

// ============ FLASH attention, 512 threads, cp.async double-buffered ============
// grid (B=64, NG=8). Online softmax, register U accumulators (slot-split).
__global__ __launch_bounds__(512) void attn_kernel(
        const float* __restrict__ qW,
        const float* __restrict__ inputs,
        float* __restrict__ upart,
        float* __restrict__ mbuf,
        float* __restrict__ lbuf)
{
    extern __shared__ float dsm[];
    float* Xs   = dsm;                 // 2*16384 (128 KB)
    float* qT   = dsm + 32768;         // [k][s] 2048
    float* lgp  = qT  + 2048;          // [kq][s][n] 8*8*64 = 4096
    float* atT  = lgp + 4096;          // [n][12] 768
    float* scs  = atT + 768;           // 8
    float* red1 = scs + 8;             // 16
    float* red2 = red1 + 16;           // 16

    int b = blockIdx.x, g = blockIdx.y;
    int t = threadIdx.x, w = t >> 5, l = t & 31;
    const int s_of = t >> 6;           // 0..7 (k-slice in phase1, slot in phase2)
    const int n_of = t & 63;

    // stage qT
#pragma unroll
    for (int p = 0; p < 4; ++p){
        int idx = t + p*512;
        qT[(idx & 255)*8 + (idx >> 8)] = qW[(size_t)b*2048 + idx];
    }

    const float* src0 = inputs + ((size_t)b*NN + g*(NTILE*TN))*IND;
#define PREFETCH(j, buf) do {                                                   \
        const float* _s = src0 + (size_t)(j)*TN*IND;                            \
        float* _d = Xs + (buf)*16384;                                           \
        _Pragma("unroll")                                                       \
        for (int p = 0; p < 8; ++p){                                            \
            int idx = t + p*512;                                                \
            int n = idx >> 6, k4 = idx & 63;                                    \
            uint32_t sa = (uint32_t)__cvta_generic_to_shared(                   \
                              &_d[(n*64 + (k4 ^ n))*4]);                        \
            asm volatile("cp.async.cg.shared.global [%0], [%1], 16;"            \
                         :: "r"(sa), "l"(_s + (size_t)n*IND + k4*4) : "memory");\
        }                                                                       \
        asm volatile("cp.async.commit_group;" ::: "memory");                    \
    } while(0)

    PREFETCH(0, 0);

    float m_run = -3.4e38f, l_run = 0.f;
    float uacc[4] = {};
    const int sh = (t >= 256) ? 4 : 0;     // phase3 slot-half
    const int e  = t & 255;
    const int e4 = e >> 2, eo = e & 3;

    for (int j = 0; j < NTILE; ++j){
        int buf = j & 1;
        if (j + 1 < NTILE){
            PREFETCH(j + 1, buf ^ 1);
            asm volatile("cp.async.wait_group 1;" ::: "memory");
        } else {
            asm volatile("cp.async.wait_group 0;" ::: "memory");
        }
        __syncthreads();                                   // S1
        const float* Xb = Xs + buf*16384;

        // ---- phase 1: logits partials; thread = (n = n_of, k-slice = s_of) ----
        {
            float acc[8] = {};
#pragma unroll
            for (int i = 0; i < 8; ++i){
                int k4 = s_of*8 + i;
                float4 x4 = *(const float4*)&Xb[(n_of*64 + (k4 ^ n_of))*4];
                int k = k4*4;
                float xv[4] = {x4.x, x4.y, x4.z, x4.w};
#pragma unroll
                for (int d = 0; d < 4; ++d){
                    float4 qa = *(const float4*)&qT[(k+d)*8];
                    float4 qb = *(const float4*)&qT[(k+d)*8 + 4];
                    acc[0] += xv[d]*qa.x; acc[1] += xv[d]*qa.y;
                    acc[2] += xv[d]*qa.z; acc[3] += xv[d]*qa.w;
                    acc[4] += xv[d]*qb.x; acc[5] += xv[d]*qb.y;
                    acc[6] += xv[d]*qb.z; acc[7] += xv[d]*qb.w;
                }
            }
#pragma unroll
            for (int s = 0; s < 8; ++s) lgp[s_of*512 + s*64 + n_of] = acc[s];
        }
        __syncthreads();                                   // S2

        // ---- phase 2: online softmax; thread owns (slot s_of, key n_of) ----
        {
            float lg = 0.f;
#pragma unroll
            for (int kq = 0; kq < 8; ++kq) lg += lgp[kq*512 + s_of*64 + n_of];
            float wm = warpMax(lg);
            if (l == 0) red1[w] = wm;
            __syncthreads();                               // S3
            float mv = fmaxf(red1[s_of*2], red1[s_of*2 + 1]);
            float m_new = fmaxf(m_run, mv);
            float ev = __expf(lg - m_new);
            atT[n_of*12 + s_of] = ev;
            float ps = warpSum(ev);
            if (l == 0) red2[w] = ps;
            float sc = __expf(m_run - m_new);
            if (n_of == 0) scs[s_of] = sc;
            m_run = m_new;
            __syncthreads();                               // S4
            l_run = l_run*sc + red2[s_of*2] + red2[s_of*2 + 1];
        }

        // ---- phase 3: U accumulation; halves own slots sh..sh+3, col e ----
        {
            float4 sv = *(const float4*)&scs[sh];
            uacc[0] *= sv.x; uacc[1] *= sv.y; uacc[2] *= sv.z; uacc[3] *= sv.w;
#pragma unroll 4
            for (int n = 0; n < TN; ++n){
                float x = Xb[(n*64 + (e4 ^ n))*4 + eo];
                float4 a = *(const float4*)&atT[n*12 + sh];
                uacc[0] += a.x*x; uacc[1] += a.y*x; uacc[2] += a.z*x; uacc[3] += a.w*x;
            }
        }
    }
#undef PREFETCH

#pragma unroll
    for (int i = 0; i < 4; ++i)
        upart[((size_t)g*ROWS + b*SS + sh + i)*IND + e] = uacc[i];
    if (n_of == 0){
        int row = b*SS + s_of;
        mbuf[(size_t)g*ROWS + row] = m_run;
        lbuf[(size_t)g*ROWS + row] = l_run;
    }
}

// ============ gemm_tiles: register-double-buffered, group-local staging ============
// acc[r] = sum over k-tiles [ktStart, ktStart+ktCount) of sA[r][k]*W[tc][k].
// MUST be called by all 512 threads with identical ktCount (barriers inside).
__device__ __forceinline__ void gemm_tiles(
        const float (*sA)[DD],
        const float* __restrict__ W,
        float* __restrict__ sWt,     // this group's staging [32][257]
        float acc[4], int tc, int ktStart, int ktCount)
{
    const float4* Wp = reinterpret_cast<const float4*>(W);
    float4 r[8];
#pragma unroll
    for (int p = 0; p < 8; ++p){
        int idx = tc + p*256;
        r[p] = __ldg(&Wp[(size_t)(idx >> 3)*64 + ktStart*8 + (idx & 7)]);
    }
    acc[0] = acc[1] = acc[2] = acc[3] = 0.f;

    for (int kt = 0; kt < ktCount; ++kt){
        __syncthreads();
#pragma unroll
        for (int p = 0; p < 8; ++p){
            int idx  = tc + p*256;
            int orow = idx >> 3, k4 = idx & 7;
            sWt[(k4*4+0)*257 + orow] = r[p].x;
            sWt[(k4*4+1)*257 + orow] = r[p].y;
            sWt[(k4*4+2)*257 + orow] = r[p].z;
            sWt[(k4*4+3)*257 + orow] = r[p].w;
        }
        __syncthreads();
        if (kt + 1 < ktCount){
#pragma unroll
            for (int p = 0; p < 8; ++p){
                int idx = tc + p*256;
                r[p] = __ldg(&Wp[(size_t)(idx >> 3)*64 + (ktStart+kt+1)*8 + (idx & 7)]);
            }
        }
        int kb = (ktStart + kt)*32;
#pragma unroll
        for (int kk = 0; kk < 8; ++kk){
            float4 a0 = *(const float4*)&sA[0][kb + kk*4];
            float4 a1 = *(const float4*)&sA[1][kb + kk*4];
            float4 a2 = *(const float4*)&sA[2][kb + kk*4];
            float4 a3 = *(const float4*)&sA[3][kb + kk*4];
            float x0 = sWt[(kk*4+0)*257 + tc];
            float x1 = sWt[(kk*4+1)*257 + tc];
            float x2 = sWt[(kk*4+2)*257 + tc];
            float x3 = sWt[(kk*4+3)*257 + tc];
            acc[0] += a0.x*x0 + a0.y*x1 + a0.z*x2 + a0.w*x3;
            acc[1] += a1.x*x0 + a1.y*x1 + a1.z*x2 + a1.w*x3;
            acc[2] += a2.x*x0 + a2.y*x1 + a2.z*x2 + a2.w*x3;
            acc[3] += a3.x*x0 + a3.y*x1 + a3.z*x2 + a3.w*x3;
        }
    }
}

// ============ POST, 512 threads: split-K GEMMs + concurrent GRU gates ============
__global__ __launch_bounds__(512) void post_kernel(
        const float* __restrict__ upart,
        const float* __restrict__ mbuf, const float* __restrict__ lbuf,
        const float* __restrict__ Wv,   const float* __restrict__ bv,
        const float* __restrict__ W_ih, const float* __restrict__ b_ih,
        const float* __restrict__ W_hh, const float* __restrict__ b_hh,
        const float* __restrict__ lng,  const float* __restrict__ lnb,
        const float* __restrict__ W1,   const float* __restrict__ b1,
        const float* __restrict__ W2,   const float* __restrict__ b2,
        const float* __restrict__ slots_in,
        float* __restrict__ dst)
{
    extern __shared__ float dsm[];
    float (*sBufA)[DD] = (float(*)[DD])(dsm);           // 1024  U / sln
    float (*sprev)[DD] = (float(*)[DD])(dsm + 1024);    // 1024
    float (*sBufB)[DD] = (float(*)[DD])(dsm + 2048);    // 1024  upd / hid
    float* sGh         = dsm + 3072;                    // 3072  gh[3][4][256]
    float (*sPar)[DD]  = (float(*)[DD])(dsm + 6144);    // 1024  split-k partials
    float* sWtA        = dsm + 7168;                    // 8224
    float* sWtB        = dsm + 15392;                   // 8224

    __shared__ float ssc[4][9];
    __shared__ float sinv[4];

    int r0 = blockIdx.x * 4;
    int t  = threadIdx.x;
    int tc = t & 255, grp = t >> 8;
    int w  = t >> 5, l = t & 31;
    float* myWt = grp ? sWtB : sWtA;

    // 1. per-row combine scales over NG=8 groups (warps 0-3, lanes 0-7)
    if (w < 4){
        int row = r0 + w;
        float mv = (l < 8) ? __ldg(&mbuf[(size_t)l*ROWS + row]) : -3.4e38f;
        float mm = mv;
        mm = fmaxf(mm, __shfl_xor_sync(0xffffffffu, mm, 1));
        mm = fmaxf(mm, __shfl_xor_sync(0xffffffffu, mm, 2));
        mm = fmaxf(mm, __shfl_xor_sync(0xffffffffu, mm, 4));
        float e  = (l < 8) ? __expf(mv - mm) : 0.f;
        float lv = (l < 8) ? __ldg(&lbuf[(size_t)l*ROWS + row]) * e : 0.f;
        lv += __shfl_xor_sync(0xffffffffu, lv, 1);
        lv += __shfl_xor_sync(0xffffffffu, lv, 2);
        lv += __shfl_xor_sync(0xffffffffu, lv, 4);
        if (l < 8) ssc[w][l] = e;
        if (l == 0) sinv[w] = 1.f / lv;
    }
    __syncthreads();

    // 2. U = (sum_g Ubar_g*sc_g)*inv ; load slots_prev (each thread 2 rows)
#pragma unroll
    for (int rr = 0; rr < 2; ++rr){
        int r = grp*2 + rr, row = r0 + r;
        float a = 0.f;
#pragma unroll
        for (int ch = 0; ch < NG; ++ch)
            a += __ldg(&upart[((size_t)ch*ROWS + row)*IND + tc]) * ssc[r][ch];
        sBufA[r][tc] = a * sinv[r];
        sprev[r][tc] = slots_in[(size_t)row*DD + tc];
    }
    // (first barrier inside gemm_tiles orders these writes)

    // 3. upd = U @ Wv^T + bv  (split-K: grp0 k0..127, grp1 k128..255)
    float acc[4];
    gemm_tiles(sBufA, Wv, myWt, acc, tc, grp*4, 4);
    if (grp == 1){
#pragma unroll
        for (int r = 0; r < 4; ++r) sPar[r][tc] = acc[r];
    }
    __syncthreads();
    if (grp == 0){
        float bb = __ldg(&bv[tc]);
#pragma unroll
        for (int r = 0; r < 4; ++r) sBufB[r][tc] = acc[r] + sPar[r][tc] + bb;
    }

    // 4. GRU gates concurrently: grp0 -> gi (W_ih on upd), grp1 -> gh (W_hh on prev)
    float gi[3][4];
#pragma unroll
    for (int j = 0; j < 3; ++j){
        const float* Wg = grp ? (W_hh + (size_t)j*DD*DD) : (W_ih + (size_t)j*DD*DD);
        const float (*Ag)[DD] = grp ? sprev : sBufB;
        gemm_tiles(Ag, Wg, myWt, acc, tc, 0, 8);
        if (grp == 0){
            float bb = __ldg(&b_ih[tc + j*256]);
#pragma unroll
            for (int r = 0; r < 4; ++r) gi[j][r] = acc[r] + bb;
        } else {
            float bb = __ldg(&b_hh[tc + j*256]);
#pragma unroll
            for (int r = 0; r < 4; ++r) sGh[(j*4 + r)*256 + tc] = acc[r] + bb;
        }
    }
    __syncthreads();

    // 5. GRU cell + residual (grp0)
    float vnew[4] = {0.f, 0.f, 0.f, 0.f};
    if (grp == 0){
#pragma unroll
        for (int r = 0; r < 4; ++r){
            float hr = sGh[(0*4 + r)*256 + tc];
            float hz = sGh[(1*4 + r)*256 + tc];
            float hn = sGh[(2*4 + r)*256 + tc];
            float rr = 1.f / (1.f + expf(-(gi[0][r] + hr)));
            float zz = 1.f / (1.f + expf(-(gi[1][r] + hz)));
            float nn = tanhf(gi[2][r] + rr*hn);
            float h  = sprev[r][tc];
            vnew[r]  = h + (1.f - zz)*nn + zz*h;
        }
    }

    // 6. LN(vnew) -> sBufA (grp0 data; all threads pass barriers)
    float lnv[4];
    block_ln4(vnew, lnv, lng, lnb, t);
    if (grp == 0){
#pragma unroll
        for (int r = 0; r < 4; ++r) sBufA[r][tc] = lnv[r];
    }

    // 7. hidden = relu(sln @ W1^T + b1) -> sBufB (split-K)
    gemm_tiles(sBufA, W1, myWt, acc, tc, grp*4, 4);
    if (grp == 1){
#pragma unroll
        for (int r = 0; r < 4; ++r) sPar[r][tc] = acc[r];
    }
    __syncthreads();
    if (grp == 0){
        float bb = __ldg(&b1[tc]);
#pragma unroll
        for (int r = 0; r < 4; ++r) sBufB[r][tc] = fmaxf(acc[r] + sPar[r][tc] + bb, 0.f);
    }

    // 8. out = vnew + hid @ W2^T + b2 (split-K)
    gemm_tiles(sBufB, W2, myWt, acc, tc, grp*4, 4);
    if (grp == 1){
#pragma unroll
        for (int r = 0; r < 4; ++r) sPar[r][tc] = acc[r];
    }
    __syncthreads();
    if (grp == 0){
        float bb = __ldg(&b2[tc]);
#pragma unroll
        for (int r = 0; r < 4; ++r)
            dst[(size_t)(r0+r)*DD + tc] = vnew[r] + acc[r] + sPar[r][tc] + bb;
    }
}

// ------------------------- host launcher -------------------------
extern "C" void kernel_launch(void* const* d_in, const int* in_sizes, int n_in,
                              void* d_out, int out_size)
{
    const float* inputs = (const float*)d_in[0];
    const float* noise  = (const float*)d_in[1];
    const float* s_mu   = (const float*)d_in[2];
    const float* s_sig  = (const float*)d_in[3];
    const float* Wq = (const float*)d_in[4];  const float* bq = (const float*)d_in[5];
    const float* Wk = (const float*)d_in[6];  /* bk = d_in[7] : dead (softmax shift-invariance) */
    const float* Wv = (const float*)d_in[8];  const float* bv = (const float*)d_in[9];
    const float* W_ih = (const float*)d_in[10]; const float* b_ih = (const float*)d_in[11];
    const float* W_hh = (const float*)d_in[12]; const float* b_hh = (const float*)d_in[13];
    const float* W1 = (const float*)d_in[14]; const float* b1 = (const float*)d_in[15];
    const float* W2 = (const float*)d_in[16]; const float* b2 = (const float*)d_in[17];
    const float* lnsg = (const float*)d_in[18]; const float* lnsb = (const float*)d_in[19];
    const float* lnmg = (const float*)d_in[20]; const float* lnmb = (const float*)d_in[21];
    float* out = (float*)d_out;
    (void)in_sizes; (void)n_in; (void)out_size;

    float *slots, *qW, *upart, *mbuf, *lbuf;
    cudaGetSymbolAddress((void**)&slots, g_slots);
    cudaGetSymbolAddress((void**)&qW,    g_qW);
    cudaGetSymbolAddress((void**)&upart, g_upart);
    cudaGetSymbolAddress((void**)&mbuf,  g_m);
    cudaGetSymbolAddress((void**)&lbuf,  g_l);

    const int ATTN_SMEM = (32768 + 2048 + 4096 + 768 + 8 + 16 + 16) * 4;   // 158,848 B
    const int POST_SMEM = (1024*3 + 3072 + 1024 + 8224*2) * 4;             //  94,464 B
    static int s_init = 0;
    if (!s_init){
        cudaFuncSetAttribute(attn_kernel, cudaFuncAttributeMaxDynamicSharedMemorySize, ATTN_SMEM);
        cudaFuncSetAttribute(post_kernel, cudaFuncAttributeMaxDynamicSharedMemorySize, POST_SMEM);
        s_init = 1;
    }

    dim3 gBN(BB, NG);

    init_slots_kernel<<<ROWS, 256>>>(noise, s_mu, s_sig, slots);

    for (int it = 0; it < 3; ++it){
        pre_kernel<<<ROWS/4, 256>>>(slots, lnsg, lnsb, Wq, bq, Wk, qW);
        attn_kernel<<<gBN, 512, ATTN_SMEM>>>(qW, inputs, upart, mbuf, lbuf);
        float* dst = (it == 2) ? out : slots;
        post_kernel<<<ROWS/4, 512, POST_SMEM>>>(upart, mbuf, lbuf, Wv, bv, W_ih, b_ih, W_hh, b_hh,
                                                lnmg, lnmb, W1, b1, W2, b2, slots, dst);
    }
}

// round 9
// speedup vs baseline: 1.5960x; 1.0543x over previous
#include <cuda_runtime.h>
#include <math.h>
#include <stdint.h>

// Problem constants
#define BB   64
#define NN   4096
#define IND  256
#define SS   8
#define DD   256
#define ROWS (BB*SS)        // 512
#define NG   16             // attention groups (blocks.y)
#define TN   32             // n's per tile
#define NTILE 8             // tiles per block (NG*NTILE*TN = 4096)

// -------- scratch (device globals; no allocation allowed) --------
__device__ float g_slots [ROWS*DD];
__device__ float g_qW    [ROWS*IND];
__device__ float g_upart [NG*ROWS*IND];   // unnormalized U partials (8 MB)
__device__ float g_m     [NG*ROWS];
__device__ float g_l     [NG*ROWS];

// -------- reductions --------
__device__ __forceinline__ float warpSum(float v){
#pragma unroll
    for (int o = 16; o > 0; o >>= 1) v += __shfl_xor_sync(0xffffffffu, v, o);
    return v;
}
__device__ __forceinline__ float warpMax(float v){
#pragma unroll
    for (int o = 16; o > 0; o >>= 1) v = fmaxf(v, __shfl_xor_sync(0xffffffffu, v, o));
    return v;
}

// -------- slots = mu + sigma * noise --------
__global__ void init_slots_kernel(const float* __restrict__ noise,
                                  const float* __restrict__ mu,
                                  const float* __restrict__ sigma,
                                  float* __restrict__ slots){
    int i  = blockIdx.x * 256 + threadIdx.x;
    int sd = i & (SS*DD - 1);
    slots[i] = mu[sd] + sigma[sd] * noise[i];
}

// Block LayerNorm (256-thread data path; callable from 256 OR 512 threads).
__device__ __forceinline__ void block_ln4(const float v[4], float o[4],
                                          const float* __restrict__ g,
                                          const float* __restrict__ b, int t)
{
    __shared__ float part[8][4];
    __shared__ float stat[4];
    int w = t >> 5, l = t & 31;
#pragma unroll
    for (int r = 0; r < 4; ++r){
        float p = warpSum(v[r]);
        if (l == 0 && w < 8) part[w][r] = p;
    }
    __syncthreads();
    if (t < 32){
        int rr = l >> 3, ww = l & 7;
        float x = part[ww][rr];
        x += __shfl_xor_sync(0xffffffffu, x, 1);
        x += __shfl_xor_sync(0xffffffffu, x, 2);
        x += __shfl_xor_sync(0xffffffffu, x, 4);
        if (ww == 0) stat[rr] = x * (1.f/256.f);
    }
    __syncthreads();
    float d[4];
#pragma unroll
    for (int r = 0; r < 4; ++r) d[r] = v[r] - stat[r];
    __syncthreads();
#pragma unroll
    for (int r = 0; r < 4; ++r){
        float p = warpSum(d[r]*d[r]);
        if (l == 0 && w < 8) part[w][r] = p;
    }
    __syncthreads();
    if (t < 32){
        int rr = l >> 3, ww = l & 7;
        float x = part[ww][rr];
        x += __shfl_xor_sync(0xffffffffu, x, 1);
        x += __shfl_xor_sync(0xffffffffu, x, 2);
        x += __shfl_xor_sync(0xffffffffu, x, 4);
        if (ww == 0) stat[rr] = rsqrtf(x * (1.f/256.f) + 1e-5f);
    }
    __syncthreads();
    int tc = t & 255;
    float gg = g[tc], bb = b[tc];
#pragma unroll
    for (int r = 0; r < 4; ++r) o[r] = d[r] * stat[r] * gg + bb;
}

// ============ PRE: LN(slots) -> q=ln@Wq^T+bq -> qW=(q@Wk)*inv_sqrt_d ============
__global__ __launch_bounds__(256) void pre_kernel(
        const float* __restrict__ slots,
        const float* __restrict__ lng, const float* __restrict__ lnb,
        const float* __restrict__ Wq,  const float* __restrict__ bq,
        const float* __restrict__ Wk,
        float* __restrict__ qW)
{
    int r0 = blockIdx.x * 4;
    int t  = threadIdx.x;
    __shared__ float s_ln[4][DD];
    __shared__ float s_q [4][DD];

    float v[4];
#pragma unroll
    for (int r = 0; r < 4; ++r) v[r] = slots[(size_t)(r0+r)*DD + t];
    float o[4];
    block_ln4(v, o, lng, lnb, t);
#pragma unroll
    for (int r = 0; r < 4; ++r) s_ln[r][t] = o[r];
    __syncthreads();

    {   // q[r, n=t] = s_ln[r] . Wq[t,:] + bq[t]
        const float4* wrow = reinterpret_cast<const float4*>(Wq + (size_t)t*DD);
        float a0=0.f, a1=0.f, a2=0.f, a3=0.f;
#pragma unroll 8
        for (int k4 = 0; k4 < 64; ++k4){
            float4 wv = __ldg(&wrow[k4]);
            int k = k4*4;
            a0 += s_ln[0][k]*wv.x + s_ln[0][k+1]*wv.y + s_ln[0][k+2]*wv.z + s_ln[0][k+3]*wv.w;
            a1 += s_ln[1][k]*wv.x + s_ln[1][k+1]*wv.y + s_ln[1][k+2]*wv.z + s_ln[1][k+3]*wv.w;
            a2 += s_ln[2][k]*wv.x + s_ln[2][k+1]*wv.y + s_ln[2][k+2]*wv.z + s_ln[2][k+3]*wv.w;
            a3 += s_ln[3][k]*wv.x + s_ln[3][k+1]*wv.y + s_ln[3][k+2]*wv.z + s_ln[3][k+3]*wv.w;
        }
        float bv = __ldg(&bq[t]);
        s_q[0][t] = a0 + bv; s_q[1][t] = a1 + bv;
        s_q[2][t] = a2 + bv; s_q[3][t] = a3 + bv;
    }
    __syncthreads();

    {   // qW[r, e=t] = (s_q[r] @ Wk[:,t]) / 16
        float c0=0.f, c1=0.f, c2=0.f, c3=0.f;
#pragma unroll 8
        for (int d = 0; d < DD; ++d){
            float wv = __ldg(&Wk[(size_t)d*IND + t]);
            c0 += s_q[0][d]*wv; c1 += s_q[1][d]*wv;
            c2 += s_q[2][d]*wv; c3 += s_q[3][d]*wv;
        }
        qW[(size_t)(r0+0)*IND + t] = c0 * 0.0625f;
        qW[(size_t)(r0+1)*IND + t] = c1 * 0.0625f;
        qW[(size_t)(r0+2)*IND + t] = c2 * 0.0625f;
        qW[(size_t)(r0+3)*IND + t] = c3 * 0.0625f;
    }
}

// ============ FLASH attention, TN=32 tiles, 2 blocks/SM ============
// grid (B=64, NG=16), 512 threads, smem ~92 KB. X slot (n,k4) at float4
// index n*64 + (k4 ^ (n&7)) — conflict-free for phase1 and phase3 patterns.
__global__ __launch_bounds__(512, 2) void attn_kernel(
        const float* __restrict__ qW,
        const float* __restrict__ inputs,
        float* __restrict__ upart,
        float* __restrict__ mbuf,
        float* __restrict__ lbuf)
{
    extern __shared__ float dsm[];
    float* Xs  = dsm;                  // 2 * 8192 floats (64 KB)
    float* qT  = dsm + 16384;          // [k][s] 2048
    float* lgp = qT  + 2048;           // [ks][s][n] 16*8*32 = 4096
    float* atT = lgp + 4096;           // [n][12] 384
    float* scs = atT + 384;            // 8

    int b = blockIdx.x, g = blockIdx.y;
    int t = threadIdx.x, w = t >> 5, l = t & 31;

    // stage qT
#pragma unroll
    for (int p = 0; p < 4; ++p){
        int idx = t + p*512;
        qT[(idx & 255)*8 + (idx >> 8)] = qW[(size_t)b*2048 + idx];
    }

    const float* src0 = inputs + ((size_t)b*NN + g*(NTILE*TN))*IND;
#define PREFETCH(j, buf) do {                                                   \
        const float* _s = src0 + (size_t)(j)*TN*IND;                            \
        float* _d = Xs + (buf)*8192;                                            \
        _Pragma("unroll")                                                       \
        for (int p = 0; p < 4; ++p){                                            \
            int idx = t + p*512;                                                \
            int n = idx >> 6, k4 = idx & 63;                                    \
            uint32_t sa = (uint32_t)__cvta_generic_to_shared(                   \
                              &_d[(n*64 + (k4 ^ (n & 7)))*4]);                  \
            asm volatile("cp.async.cg.shared.global [%0], [%1], 16;"            \
                         :: "r"(sa), "l"(_s + (size_t)n*IND + k4*4) : "memory");\
        }                                                                       \
        asm volatile("cp.async.commit_group;" ::: "memory");                    \
    } while(0)

    PREFETCH(0, 0);

    float m_run = -3.4e38f, l_run = 0.f;
    float uacc[4] = {};
    const int sh = (t >= 256) ? 4 : 0;     // phase3 slot-half
    const int e  = t & 255;
    const int e4 = e >> 2, eo = e & 3;
    const int ks = t >> 5;                 // phase1 k-slice (= warp id)
    const int pn = t & 31;                 // phase1 n (= lane)

    for (int j = 0; j < NTILE; ++j){
        int buf = j & 1;
        if (j + 1 < NTILE){
            PREFETCH(j + 1, buf ^ 1);
            asm volatile("cp.async.wait_group 1;" ::: "memory");
        } else {
            asm volatile("cp.async.wait_group 0;" ::: "memory");
        }
        __syncthreads();                                   // S1: tile ready
        const float* Xb = Xs + buf*8192;

        // ---- phase 1: logits partials; warp = k-slice (16 k), lane = n ----
        {
            float acc[8] = {};
#pragma unroll
            for (int i = 0; i < 4; ++i){
                int k4 = ks*4 + i;
                float4 x4 = *(const float4*)&Xb[(pn*64 + (k4 ^ (pn & 7)))*4];
                int k = k4*4;
                float xv[4] = {x4.x, x4.y, x4.z, x4.w};
#pragma unroll
                for (int d = 0; d < 4; ++d){
                    // qT addresses are warp-uniform -> smem broadcast
                    float4 qa = *(const float4*)&qT[(k+d)*8];
                    float4 qb = *(const float4*)&qT[(k+d)*8 + 4];
                    acc[0] += xv[d]*qa.x; acc[1] += xv[d]*qa.y;
                    acc[2] += xv[d]*qa.z; acc[3] += xv[d]*qa.w;
                    acc[4] += xv[d]*qb.x; acc[5] += xv[d]*qb.y;
                    acc[6] += xv[d]*qb.z; acc[7] += xv[d]*qb.w;
                }
            }
#pragma unroll
            for (int s = 0; s < 8; ++s) lgp[ks*256 + s*32 + pn] = acc[s];
        }
        __syncthreads();                                   // S2: lgp ready

        // ---- phase 2: online softmax; warp w<8 owns slot w, lane = n ----
        if (w < 8){
            float lg = 0.f;
#pragma unroll
            for (int kq = 0; kq < 16; ++kq) lg += lgp[kq*256 + w*32 + l];
            float mv = warpMax(lg);
            float m_new = fmaxf(m_run, mv);
            float ev = __expf(lg - m_new);
            atT[l*12 + w] = ev;
            float sum = warpSum(ev);
            float sc  = __expf(m_run - m_new);
            l_run = l_run*sc + sum;
            m_run = m_new;
            if (l == 0) scs[w] = sc;
        }
        __syncthreads();                                   // S3: atT/scs ready

        // ---- phase 3: U accumulation; halves own slots sh..sh+3, col e ----
        {
            float4 sv = *(const float4*)&scs[sh];
            uacc[0] *= sv.x; uacc[1] *= sv.y; uacc[2] *= sv.z; uacc[3] *= sv.w;
#pragma unroll 4
            for (int n = 0; n < TN; ++n){
                float x = Xb[(n*64 + (e4 ^ (n & 7)))*4 + eo];
                float4 a = *(const float4*)&atT[n*12 + sh];
                uacc[0] += a.x*x; uacc[1] += a.y*x; uacc[2] += a.z*x; uacc[3] += a.w*x;
            }
        }
        __syncthreads();   // S4: phase3 reads done before next prefetch lands
    }
#undef PREFETCH

#pragma unroll
    for (int i = 0; i < 4; ++i)
        upart[((size_t)g*ROWS + b*SS + sh + i)*IND + e] = uacc[i];
    if (w < 8 && l == 0){
        int row = b*SS + w;
        mbuf[(size_t)g*ROWS + row] = m_run;
        lbuf[(size_t)g*ROWS + row] = l_run;
    }
}

// ============ gemm_tiles: register-double-buffered, group-local staging ============
__device__ __forceinline__ void gemm_tiles(
        const float (*sA)[DD],
        const float* __restrict__ W,
        float* __restrict__ sWt,     // this group's staging [32][257]
        float acc[4], int tc, int ktStart, int ktCount)
{
    const float4* Wp = reinterpret_cast<const float4*>(W);
    float4 r[8];
#pragma unroll
    for (int p = 0; p < 8; ++p){
        int idx = tc + p*256;
        r[p] = __ldg(&Wp[(size_t)(idx >> 3)*64 + ktStart*8 + (idx & 7)]);
    }
    acc[0] = acc[1] = acc[2] = acc[3] = 0.f;

    for (int kt = 0; kt < ktCount; ++kt){
        __syncthreads();
#pragma unroll
        for (int p = 0; p < 8; ++p){
            int idx  = tc + p*256;
            int orow = idx >> 3, k4 = idx & 7;
            sWt[(k4*4+0)*257 + orow] = r[p].x;
            sWt[(k4*4+1)*257 + orow] = r[p].y;
            sWt[(k4*4+2)*257 + orow] = r[p].z;
            sWt[(k4*4+3)*257 + orow] = r[p].w;
        }
        __syncthreads();
        if (kt + 1 < ktCount){
#pragma unroll
            for (int p = 0; p < 8; ++p){
                int idx = tc + p*256;
                r[p] = __ldg(&Wp[(size_t)(idx >> 3)*64 + (ktStart+kt+1)*8 + (idx & 7)]);
            }
        }
        int kb = (ktStart + kt)*32;
#pragma unroll
        for (int kk = 0; kk < 8; ++kk){
            float4 a0 = *(const float4*)&sA[0][kb + kk*4];
            float4 a1 = *(const float4*)&sA[1][kb + kk*4];
            float4 a2 = *(const float4*)&sA[2][kb + kk*4];
            float4 a3 = *(const float4*)&sA[3][kb + kk*4];
            float x0 = sWt[(kk*4+0)*257 + tc];
            float x1 = sWt[(kk*4+1)*257 + tc];
            float x2 = sWt[(kk*4+2)*257 + tc];
            float x3 = sWt[(kk*4+3)*257 + tc];
            acc[0] += a0.x*x0 + a0.y*x1 + a0.z*x2 + a0.w*x3;
            acc[1] += a1.x*x0 + a1.y*x1 + a1.z*x2 + a1.w*x3;
            acc[2] += a2.x*x0 + a2.y*x1 + a2.z*x2 + a2.w*x3;
            acc[3] += a3.x*x0 + a3.y*x1 + a3.z*x2 + a3.w*x3;
        }
    }
}

// ============ POST, 512 threads: split-K GEMMs + concurrent GRU gates ============
__global__ __launch_bounds__(512) void post_kernel(
        const float* __restrict__ upart,
        const float* __restrict__ mbuf, const float* __restrict__ lbuf,
        const float* __restrict__ Wv,   const float* __restrict__ bv,
        const float* __restrict__ W_ih, const float* __restrict__ b_ih,
        const float* __restrict__ W_hh, const float* __restrict__ b_hh,
        const float* __restrict__ lng,  const float* __restrict__ lnb,
        const float* __restrict__ W1,   const float* __restrict__ b1,
        const float* __restrict__ W2,   const float* __restrict__ b2,
        const float* __restrict__ slots_in,
        float* __restrict__ dst)
{
    extern __shared__ float dsm[];
    float (*sBufA)[DD] = (float(*)[DD])(dsm);           // 1024  U / sln
    float (*sprev)[DD] = (float(*)[DD])(dsm + 1024);    // 1024
    float (*sBufB)[DD] = (float(*)[DD])(dsm + 2048);    // 1024  upd / hid
    float* sGh         = dsm + 3072;                    // 3072  gh[3][4][256]
    float (*sPar)[DD]  = (float(*)[DD])(dsm + 6144);    // 1024  split-k partials
    float* sWtA        = dsm + 7168;                    // 8224
    float* sWtB        = dsm + 15392;                   // 8224

    __shared__ float ssc[4][17];
    __shared__ float sinv[4];

    int r0 = blockIdx.x * 4;
    int t  = threadIdx.x;
    int tc = t & 255, grp = t >> 8;
    int w  = t >> 5, l = t & 31;
    float* myWt = grp ? sWtB : sWtA;

    // 1. per-row combine scales over NG=16 groups (warps 0-3, lanes 0-15)
    if (w < 4){
        int row = r0 + w;
        float mv = (l < NG) ? __ldg(&mbuf[(size_t)l*ROWS + row]) : -3.4e38f;
        float mm = mv;
        mm = fmaxf(mm, __shfl_xor_sync(0xffffffffu, mm, 1));
        mm = fmaxf(mm, __shfl_xor_sync(0xffffffffu, mm, 2));
        mm = fmaxf(mm, __shfl_xor_sync(0xffffffffu, mm, 4));
        mm = fmaxf(mm, __shfl_xor_sync(0xffffffffu, mm, 8));
        float e  = (l < NG) ? __expf(mv - mm) : 0.f;
        float lv = (l < NG) ? __ldg(&lbuf[(size_t)l*ROWS + row]) * e : 0.f;
        lv += __shfl_xor_sync(0xffffffffu, lv, 1);
        lv += __shfl_xor_sync(0xffffffffu, lv, 2);
        lv += __shfl_xor_sync(0xffffffffu, lv, 4);
        lv += __shfl_xor_sync(0xffffffffu, lv, 8);
        if (l < NG) ssc[w][l] = e;
        if (l == 0) sinv[w] = 1.f / lv;
    }
    __syncthreads();

    // 2. U = (sum_g Ubar_g*sc_g)*inv ; load slots_prev (each thread 2 rows)
#pragma unroll
    for (int rr = 0; rr < 2; ++rr){
        int r = grp*2 + rr, row = r0 + r;
        float a = 0.f;
#pragma unroll
        for (int ch = 0; ch < NG; ++ch)
            a += __ldg(&upart[((size_t)ch*ROWS + row)*IND + tc]) * ssc[r][ch];
        sBufA[r][tc] = a * sinv[r];
        sprev[r][tc] = slots_in[(size_t)row*DD + tc];
    }
    // (first barrier inside gemm_tiles orders these writes)

    // 3. upd = U @ Wv^T + bv  (split-K)
    float acc[4];
    gemm_tiles(sBufA, Wv, myWt, acc, tc, grp*4, 4);
    if (grp == 1){
#pragma unroll
        for (int r = 0; r < 4; ++r) sPar[r][tc] = acc[r];
    }
    __syncthreads();
    if (grp == 0){
        float bb = __ldg(&bv[tc]);
#pragma unroll
        for (int r = 0; r < 4; ++r) sBufB[r][tc] = acc[r] + sPar[r][tc] + bb;
    }

    // 4. GRU gates concurrently: grp0 -> gi (W_ih on upd), grp1 -> gh (W_hh on prev)
    float gi[3][4];
#pragma unroll
    for (int j = 0; j < 3; ++j){
        const float* Wg = grp ? (W_hh + (size_t)j*DD*DD) : (W_ih + (size_t)j*DD*DD);
        const float (*Ag)[DD] = grp ? sprev : sBufB;
        gemm_tiles(Ag, Wg, myWt, acc, tc, 0, 8);
        if (grp == 0){
            float bb = __ldg(&b_ih[tc + j*256]);
#pragma unroll
            for (int r = 0; r < 4; ++r) gi[j][r] = acc[r] + bb;
        } else {
            float bb = __ldg(&b_hh[tc + j*256]);
#pragma unroll
            for (int r = 0; r < 4; ++r) sGh[(j*4 + r)*256 + tc] = acc[r] + bb;
        }
    }
    __syncthreads();

    // 5. GRU cell + residual (grp0)
    float vnew[4] = {0.f, 0.f, 0.f, 0.f};
    if (grp == 0){
#pragma unroll
        for (int r = 0; r < 4; ++r){
            float hr = sGh[(0*4 + r)*256 + tc];
            float hz = sGh[(1*4 + r)*256 + tc];
            float hn = sGh[(2*4 + r)*256 + tc];
            float rr = 1.f / (1.f + expf(-(gi[0][r] + hr)));
            float zz = 1.f / (1.f + expf(-(gi[1][r] + hz)));
            float nn = tanhf(gi[2][r] + rr*hn);
            float h  = sprev[r][tc];
            vnew[r]  = h + (1.f - zz)*nn + zz*h;
        }
    }

    // 6. LN(vnew) -> sBufA (grp0 data; all threads pass barriers)
    float lnv[4];
    block_ln4(vnew, lnv, lng, lnb, t);
    if (grp == 0){
#pragma unroll
        for (int r = 0; r < 4; ++r) sBufA[r][tc] = lnv[r];
    }

    // 7. hidden = relu(sln @ W1^T + b1) -> sBufB (split-K)
    gemm_tiles(sBufA, W1, myWt, acc, tc, grp*4, 4);
    if (grp == 1){
#pragma unroll
        for (int r = 0; r < 4; ++r) sPar[r][tc] = acc[r];
    }
    __syncthreads();
    if (grp == 0){
        float bb = __ldg(&b1[tc]);
#pragma unroll
        for (int r = 0; r < 4; ++r) sBufB[r][tc] = fmaxf(acc[r] + sPar[r][tc] + bb, 0.f);
    }

    // 8. out = vnew + hid @ W2^T + b2 (split-K)
    gemm_tiles(sBufB, W2, myWt, acc, tc, grp*4, 4);
    if (grp == 1){
#pragma unroll
        for (int r = 0; r < 4; ++r) sPar[r][tc] = acc[r];
    }
    __syncthreads();
    if (grp == 0){
        float bb = __ldg(&b2[tc]);
#pragma unroll
        for (int r = 0; r < 4; ++r)
            dst[(size_t)(r0+r)*DD + tc] = vnew[r] + acc[r] + sPar[r][tc] + bb;
    }
}

// ------------------------- host launcher -------------------------
extern "C" void kernel_launch(void* const* d_in, const int* in_sizes, int n_in,
                              void* d_out, int out_size)
{
    const float* inputs = (const float*)d_in[0];
    const float* noise  = (const float*)d_in[1];
    const float* s_mu   = (const float*)d_in[2];
    const float* s_sig  = (const float*)d_in[3];
    const float* Wq = (const float*)d_in[4];  const float* bq = (const float*)d_in[5];
    const float* Wk = (const float*)d_in[6];  /* bk = d_in[7] : dead (softmax shift-invariance) */
    const float* Wv = (const float*)d_in[8];  const float* bv = (const float*)d_in[9];
    const float* W_ih = (const float*)d_in[10]; const float* b_ih = (const float*)d_in[11];
    const float* W_hh = (const float*)d_in[12]; const float* b_hh = (const float*)d_in[13];
    const float* W1 = (const float*)d_in[14]; const float* b1 = (const float*)d_in[15];
    const float* W2 = (const float*)d_in[16]; const float* b2 = (const float*)d_in[17];
    const float* lnsg = (const float*)d_in[18]; const float* lnsb = (const float*)d_in[19];
    const float* lnmg = (const float*)d_in[20]; const float* lnmb = (const float*)d_in[21];
    float* out = (float*)d_out;
    (void)in_sizes; (void)n_in; (void)out_size;

    float *slots, *qW, *upart, *mbuf, *lbuf;
    cudaGetSymbolAddress((void**)&slots, g_slots);
    cudaGetSymbolAddress((void**)&qW,    g_qW);
    cudaGetSymbolAddress((void**)&upart, g_upart);
    cudaGetSymbolAddress((void**)&mbuf,  g_m);
    cudaGetSymbolAddress((void**)&lbuf,  g_l);

    const int ATTN_SMEM = (16384 + 2048 + 4096 + 384 + 8) * 4;   // 91,680 B -> 2 blocks/SM
    const int POST_SMEM = (1024*3 + 3072 + 1024 + 8224*2) * 4;   // 94,464 B
    static int s_init = 0;
    if (!s_init){
        cudaFuncSetAttribute(attn_kernel, cudaFuncAttributeMaxDynamicSharedMemorySize, ATTN_SMEM);
        cudaFuncSetAttribute(post_kernel, cudaFuncAttributeMaxDynamicSharedMemorySize, POST_SMEM);
        s_init = 1;
    }

    dim3 gBN(BB, NG);

    init_slots_kernel<<<ROWS, 256>>>(noise, s_mu, s_sig, slots);

    for (int it = 0; it < 3; ++it){
        pre_kernel<<<ROWS/4, 256>>>(slots, lnsg, lnsb, Wq, bq, Wk, qW);
        attn_kernel<<<gBN, 512, ATTN_SMEM>>>(qW, inputs, upart, mbuf, lbuf);
        float* dst = (it == 2) ? out : slots;
        post_kernel<<<ROWS/4, 512, POST_SMEM>>>(upart, mbuf, lbuf, Wv, bv, W_ih, b_ih, W_hh, b_hh,
                                                lnmg, lnmb, W1, b1, W2, b2, slots, dst);
    }
}